// round 7
// baseline (speedup 1.0000x reference)
#include <cuda_runtime.h>

// ---------------------------------------------------------------------------
// Sparse 3-layer conv net (ME-style). Round 7:
//  - gather tables in COLUMN-MAJOR layout tab[k*stride + o] -> coalesced builds
//  - layer1: 2 rows/warp, int2 table pair-loads
//  - layer2: 2 rows/warp, repacked W2 (channel pairs adjacent), f32x2 FMA,
//            x staged pre-duplicated in smem
//  - layer3: dense GEMM (f32x2) + gather-sum epilogue
// ---------------------------------------------------------------------------

#define N1S 300004        // stride capacity for fine tables (mult of 4)
#define N2S 262148        // stride capacity for coarse tables (mult of 4)
#define N1_MAX 300001
#define N2_MAX 262145

__device__ __align__(16) int g_tab1[27 * N1S];
__device__ __align__(16) int g_tab2[8 * N2S];
__device__ __align__(16) int g_tab3[27 * N2S];
__device__ float g_h1[(N1_MAX - 1) * 64];
__device__ float g_h2[(N2_MAX - 1) * 64];
__device__ float g_W2p[8 * 64 * 64];              // pairs (c, c+32) adjacent
__device__ float g_W3r[64 * 216];                 // W3 repacked: [f][k*8+c]
__device__ float g_S3[(N2_MAX - 1) * 216];        // per-input transforms, layer3

typedef unsigned long long ull;

__device__ __forceinline__ ull pack2(float a, float b) {
    ull r;
    asm("mov.b64 %0, {%1, %2};" : "=l"(r)
        : "r"(__float_as_uint(a)), "r"(__float_as_uint(b)));
    return r;
}
__device__ __forceinline__ ull dup2(float a) {
    ull r;
    asm("mov.b64 %0, {%1, %1};" : "=l"(r) : "r"(__float_as_uint(a)));
    return r;
}
__device__ __forceinline__ float lo2(ull v) {
    unsigned int x;
    asm("{ .reg .b32 hi; mov.b64 {%0, hi}, %1; }" : "=r"(x) : "l"(v));
    return __uint_as_float(x);
}
__device__ __forceinline__ float hi2(ull v) {
    unsigned int x;
    asm("{ .reg .b32 lo; mov.b64 {lo, %0}, %1; }" : "=r"(x) : "l"(v));
    return __uint_as_float(x);
}

// ---------------- table fill: vectorized -1 ----------------
__global__ void fill_kernel(int which, int n4) {
    int4* p = (which == 0) ? (int4*)g_tab1 : (which == 1) ? (int4*)g_tab2
                                                          : (int4*)g_tab3;
    const int4 v = make_int4(-1, -1, -1, -1);
    int i = blockIdx.x * blockDim.x + threadIdx.x;
    int stride = gridDim.x * blockDim.x;
    for (; i < n4; i += stride) p[i] = v;
}

// ---------------- table build: tab[k*s + out] = in  (coalesced: out sorted) --
__global__ void build_kernel(const int* __restrict__ m_in,
                             const int* __restrict__ m_out,
                             int which, int s, int L) {
    int* tab = (which == 0) ? g_tab1 : (which == 1) ? g_tab2 : g_tab3;
    int k = blockIdx.y;
    const int* mi = m_in + k * L;
    const int* mo = m_out + k * L;
    int* col = tab + k * s;
    int i = blockIdx.x * blockDim.x + threadIdx.x;
    int stride = gridDim.x * blockDim.x;
    for (; i < L; i += stride) col[mo[i]] = mi[i];
}

// ---------------- W2 repack: pairs (c, c+32) adjacent ------------------------
// g_W2p[((k*64+f)*32 + (c&31))*2 + (c>>5)] = W2[(k*64+f)*64 + c]
__global__ void repack_w2_kernel(const float* __restrict__ W2) {
    int i = blockIdx.x * blockDim.x + threadIdx.x;
    if (i < 8 * 64 * 64) {
        int kf = i >> 6, c = i & 63;
        g_W2p[(kf * 32 + (c & 31)) * 2 + (c >> 5)] = W2[i];
    }
}

// ---------------- W3 repack: W3r[f*216 + k*8 + c] = W3[k][f][c] --------------
__global__ void repack_w3_kernel(const float* __restrict__ W3) {
    int i = blockIdx.x * blockDim.x + threadIdx.x;
    if (i < 27 * 512) {
        int k = i >> 9, rem = i & 511, f = rem >> 3, c = rem & 7;
        g_W3r[f * 216 + k * 8 + c] = W3[i];
    }
}

// ---------------- layer 1: 27 offsets, 8 -> 64, ReLU, 2 rows/warp ------------
__global__ void __launch_bounds__(256) layer1_kernel(
    const float* __restrict__ feats, const float* __restrict__ W1,
    const float* __restrict__ b1, int n1, int s1) {
    extern __shared__ float sW1[];           // 13824 floats
    for (int i = threadIdx.x; i < 27 * 512; i += 256) sW1[i] = W1[i];
    __syncthreads();

    int lane = threadIdx.x & 31;
    int gw = (blockIdx.x * 256 + threadIdx.x) >> 5;
    int nw = (gridDim.x * 256) >> 5;
    float bias0 = b1[lane], bias1 = b1[lane + 32];
    int npairs = (n1 + 1) >> 1;

    for (int p = gw; p < npairs; p += nw) {
        int o0 = 2 * p, o1 = o0 + 1;
        bool r1v = (o1 < n1);
        float a00 = bias0, a01 = bias1, a10 = bias0, a11 = bias1;
        for (int k = 0; k < 27; k++) {
            int2 tt = *(const int2*)(g_tab1 + k * s1 + o0);
            int i0 = tt.x;
            int i1 = r1v ? tt.y : -1;
            if (i0 < 0 && i1 < 0) continue;
            float xf = 0.f;
            if (lane < 8) { if (i0 >= 0) xf = feats[i0 * 8 + lane]; }
            else if (lane < 16) { if (i1 >= 0) xf = feats[i1 * 8 + lane - 8]; }
            const float* w = sW1 + k * 512 + lane;
            #pragma unroll
            for (int f = 0; f < 8; f++) {
                float v0 = __shfl_sync(0xffffffffu, xf, f);
                float v1 = __shfl_sync(0xffffffffu, xf, 8 + f);
                float w0 = w[f * 64], w1 = w[f * 64 + 32];
                a00 = fmaf(v0, w0, a00);
                a01 = fmaf(v0, w1, a01);
                a10 = fmaf(v1, w0, a10);
                a11 = fmaf(v1, w1, a11);
            }
        }
        g_h1[o0 * 64 + lane]      = fmaxf(a00, 0.f);
        g_h1[o0 * 64 + lane + 32] = fmaxf(a01, 0.f);
        if (r1v) {
            g_h1[o1 * 64 + lane]      = fmaxf(a10, 0.f);
            g_h1[o1 * 64 + lane + 32] = fmaxf(a11, 0.f);
        }
    }
}

// ---------------- layer 2: 8 offsets, 64 -> 64, ReLU, 2 rows/warp ------------
// W2p (128 KB) in smem as (c,c+32) float2 pairs; x staged pre-duplicated as
// f32x2 in smem; inner loop: 1 LDS.64 weight + 2 LDS.64 bcast + 2 FFMA2 per f.
__global__ void __launch_bounds__(512) layer2_kernel(
    const float* __restrict__ b2, int n2, int s2) {
    extern __shared__ float sm2[];
    float* sW = sm2;                          // 32768 floats (repacked)
    ull* sXd = (ull*)(sm2 + 32768);           // 16 warps * 128 u64
    {
        const float4* src = (const float4*)g_W2p;
        float4* dst = (float4*)sW;
        for (int i = threadIdx.x; i < 8192; i += 512) dst[i] = src[i];
    }
    __syncthreads();

    int lane = threadIdx.x & 31;
    int warp = threadIdx.x >> 5;
    ull* xd = sXd + warp * 128;
    int gw = (blockIdx.x * 512 + threadIdx.x) >> 5;
    int nw = (gridDim.x * 512) >> 5;
    ull bias = pack2(b2[lane], b2[lane + 32]);
    int npairs = (n2 + 1) >> 1;

    for (int p = gw; p < npairs; p += nw) {
        int o0 = 2 * p, o1 = o0 + 1;
        bool r1v = (o1 < n2);
        ull a0 = bias, a1 = bias;
        for (int k = 0; k < 8; k++) {
            int2 tt = *(const int2*)(g_tab2 + k * s2 + o0);
            int i0 = tt.x;
            int i1 = r1v ? tt.y : -1;
            if (i0 < 0 && i1 < 0) continue;
            float2 x0 = make_float2(0.f, 0.f), x1 = make_float2(0.f, 0.f);
            if (i0 >= 0) x0 = ((const float2*)g_h1)[i0 * 32 + lane];
            if (i1 >= 0) x1 = ((const float2*)g_h1)[i1 * 32 + lane];
            xd[2 * lane]           = dup2(x0.x);
            xd[2 * lane + 1]       = dup2(x0.y);
            xd[64 + 2 * lane]      = dup2(x1.x);
            xd[64 + 2 * lane + 1]  = dup2(x1.y);
            __syncwarp();
            const ull* wp = (const ull*)sW + k * 2048 + lane;
            #pragma unroll
            for (int f = 0; f < 64; f++) {
                ull wv = wp[f * 32];
                ull xv0 = xd[f];
                ull xv1 = xd[64 + f];
                asm("fma.rn.f32x2 %0, %1, %2, %0;" : "+l"(a0) : "l"(wv), "l"(xv0));
                asm("fma.rn.f32x2 %0, %1, %2, %0;" : "+l"(a1) : "l"(wv), "l"(xv1));
            }
            __syncwarp();
        }
        g_h2[o0 * 64 + lane]      = fmaxf(lo2(a0), 0.f);
        g_h2[o0 * 64 + lane + 32] = fmaxf(hi2(a0), 0.f);
        if (r1v) {
            g_h2[o1 * 64 + lane]      = fmaxf(lo2(a1), 0.f);
            g_h2[o1 * 64 + lane + 32] = fmaxf(hi2(a1), 0.f);
        }
    }
}

// ---------------- layer 3 GEMM: S3[n2][216] = H2[n2][64] @ W3r[64][216] ------
__global__ void __launch_bounds__(256) l3gemm_kernel(int n2) {
    extern __shared__ float sm3[];
    float* sW = sm3;                 // 64 * 224
    float* sX = sm3 + 64 * 224;      // 64 * 64

    for (int i = threadIdx.x; i < 64 * 224; i += 256) {
        int k = i / 224, c = i - k * 224;
        sW[i] = (c < 216) ? g_W3r[k * 216 + c] : 0.f;
    }
    int base = blockIdx.x << 6;
    for (int i = threadIdx.x; i < 1024; i += 256) {   // 64 rows * 16 float4
        int r = i >> 4, q = i & 15;
        int row = base + r;
        float4 v = make_float4(0.f, 0.f, 0.f, 0.f);
        if (row < n2) v = ((const float4*)g_h2)[row * 16 + q];
        ((float4*)sX)[i] = v;
    }
    __syncthreads();

    int lane = threadIdx.x & 31, warp = threadIdx.x >> 5;
    const float* xw = sX + warp * 512;        // 8 rows of 64

    ull acc[4][7];
    #pragma unroll
    for (int p = 0; p < 4; p++)
        #pragma unroll
        for (int j = 0; j < 7; j++) acc[p][j] = 0ull;

    #pragma unroll 4
    for (int k = 0; k < 64; k++) {
        ull xp[4];
        #pragma unroll
        for (int p = 0; p < 4; p++)
            xp[p] = pack2(xw[(2 * p) * 64 + k], xw[(2 * p + 1) * 64 + k]);
        const float* wr = sW + k * 224 + lane;
        #pragma unroll
        for (int j = 0; j < 7; j++) {
            ull ww = dup2(wr[j * 32]);
            #pragma unroll
            for (int p = 0; p < 4; p++)
                asm("fma.rn.f32x2 %0, %1, %2, %0;"
                    : "+l"(acc[p][j]) : "l"(xp[p]), "l"(ww));
        }
    }

    int rbase = base + warp * 8;
    #pragma unroll
    for (int p = 0; p < 4; p++) {
        int r0 = rbase + 2 * p;
        #pragma unroll
        for (int j = 0; j < 7; j++) {
            int col = (j << 5) + lane;
            if (col < 216) {
                if (r0 < n2)     g_S3[r0 * 216 + col]       = lo2(acc[p][j]);
                if (r0 + 1 < n2) g_S3[(r0 + 1) * 216 + col] = hi2(acc[p][j]);
            }
        }
    }
}

// ---------------- layer 3 gather-sum -----------------------------------------
__global__ void __launch_bounds__(256) l3gs_kernel(
    const float* __restrict__ b3, float* __restrict__ out, int n2, int s3) {
    __shared__ int st[32 * 27];
    int base = blockIdx.x << 5;
    for (int i = threadIdx.x; i < 27 * 32; i += 256) {
        int k = i >> 5, r = i & 31;            // coalesced per-k column read
        int o = base + r;
        st[r * 27 + k] = (o < n2) ? g_tab3[k * s3 + o] : -1;
    }
    __syncthreads();

    int lane = threadIdx.x & 31, warp = threadIdx.x >> 5;
    int sub = lane >> 3, c = lane & 7;
    int lo = (warp << 2) + sub;               // local output 0..31
    int o = base + lo;
    const int* t = st + lo * 27;
    float acc = 0.f;
    #pragma unroll
    for (int k = 0; k < 27; k++) {
        int idx = t[k];
        float v = 0.f;
        if (idx >= 0) v = g_S3[idx * 216 + (k << 3) + c];
        acc += v;
    }
    if (o < n2) out[(o << 3) + c] = acc + b3[c];
}

// ---------------------------------------------------------------------------
extern "C" void kernel_launch(void* const* d_in, const int* in_sizes, int n_in,
                              void* d_out, int out_size) {
    const float* feats = (const float*)d_in[0];
    const float* W1    = (const float*)d_in[1];
    const float* b1    = (const float*)d_in[2];
    const float* W2    = (const float*)d_in[3];
    const float* b2    = (const float*)d_in[4];
    const float* W3    = (const float*)d_in[5];
    const float* b3    = (const float*)d_in[6];
    const int* map1_in  = (const int*)d_in[7];
    const int* map1_out = (const int*)d_in[8];
    const int* map2_in  = (const int*)d_in[9];
    const int* map2_out = (const int*)d_in[10];
    const int* map3_in  = (const int*)d_in[11];
    const int* map3_out = (const int*)d_in[12];
    float* out = (float*)d_out;

    int n1 = in_sizes[0] / 8;
    int n2 = out_size / 8;
    int L1 = in_sizes[7] / 27;
    int L2 = in_sizes[9] / 8;
    int L3 = in_sizes[11] / 27;
    int s1 = (n1 + 5) & ~3;                   // column stride (mult of 4, > n1+1)
    int s2 = (n2 + 5) & ~3;

    cudaFuncSetAttribute(layer1_kernel, cudaFuncAttributeMaxDynamicSharedMemorySize, 27 * 512 * 4);
    cudaFuncSetAttribute(layer2_kernel, cudaFuncAttributeMaxDynamicSharedMemorySize, 32768 * 4 + 16 * 128 * 8);
    cudaFuncSetAttribute(l3gemm_kernel, cudaFuncAttributeMaxDynamicSharedMemorySize, (64 * 224 + 64 * 64) * 4);

    // 1) fill gather tables with -1 (int4-vectorized)
    fill_kernel<<<592, 256>>>(0, (27 * s1) / 4);
    fill_kernel<<<296, 256>>>(1, (8 * s2) / 4);
    fill_kernel<<<592, 256>>>(2, (27 * s2) / 4);

    // 2) invert pair lists (coalesced column-major stores)
    {
        dim3 g1((unsigned)min((L1 + 255) / 256, 1184), 27);
        dim3 g2((unsigned)min((L2 + 255) / 256, 1184), 8);
        dim3 g3((unsigned)min((L3 + 255) / 256, 1184), 27);
        build_kernel<<<g1, 256>>>(map1_in, map1_out, 0, s1, L1);
        build_kernel<<<g2, 256>>>(map2_in, map2_out, 1, s2, L2);
        build_kernel<<<g3, 256>>>(map3_in, map3_out, 2, s2, L3);
    }

    // 3) weight repacks
    repack_w2_kernel<<<128, 256>>>(W2);
    repack_w3_kernel<<<54, 256>>>(W3);

    // 4) layers
    layer1_kernel<<<592, 256, 27 * 512 * 4>>>(feats, W1, b1, n1, s1);
    layer2_kernel<<<148, 512, 32768 * 4 + 16 * 128 * 8>>>(b2, n2, s2);
    l3gemm_kernel<<<(n2 + 63) / 64, 256, (64 * 224 + 64 * 64) * 4>>>(n2);
    l3gs_kernel<<<(n2 + 31) / 32, 256>>>(b3, out, n2, s2);
}